// round 10
// baseline (speedup 1.0000x reference)
#include <cuda_runtime.h>
#include <cuda_bf16.h>

// Shapes: B=32, S=2048, I=128, A=128, H=256, K=8, ACTIVE=3 (structurally k=0,1,2)
#define NB 32
#define NS 2048
#define NI 128
#define NA 128
#define NH 256
#define NK 8
#define KACT 3
#define CHUNKS 32
#define ROWS_PER_BLOCK (NS / CHUNKS)       // 64
#define ROWS_PER_WARP (ROWS_PER_BLOCK / 8) // 8
#define PREF 4

// Device scratch (allocation-free rule: __device__ globals; zero-initialized)
__device__ float g_u[KACT][NI];
__device__ float g_hpre[KACT][NH];
__device__ __align__(16) float g_ypart[NB][CHUNKS][KACT * NI];
__device__ int   g_bcnt[NB];

// ---------------------------------------------------------------------------
// Prologue (9 blocks x 1024 threads):
//   blocks 0..2 : k-block. q[k][a] = sum_h rim*Wq, then u[k][i] = Wk[k][i][:].q
//   blocks 3..8 : (k, h-half) hpre
// ---------------------------------------------------------------------------
__global__ __launch_bounds__(1024) void prologue_kernel(
    const float* __restrict__ rim, const float* __restrict__ Wq,
    const float* __restrict__ Wk, const float* __restrict__ Whh,
    const float* __restrict__ bias)
{
    const int tid = threadIdx.x;
    const int bid = blockIdx.x;

    if (bid < KACT) {
        const int k = bid;
        __shared__ float qp[8][NA];
        __shared__ __align__(16) float qs[NA];

        {
            const int a    = tid & 127;
            const int part = tid >> 7;
            const int h0   = part * 32;
            const float* __restrict__ wq = Wq + ((size_t)(k * NH + h0)) * NA + a;
            const float* __restrict__ rk = rim + k * NH + h0;
            float acc0 = 0.f, acc1 = 0.f, acc2 = 0.f, acc3 = 0.f;
            #pragma unroll
            for (int h = 0; h < 32; h += 4) {
                acc0 += rk[h + 0] * wq[(size_t)(h + 0) * NA];
                acc1 += rk[h + 1] * wq[(size_t)(h + 1) * NA];
                acc2 += rk[h + 2] * wq[(size_t)(h + 2) * NA];
                acc3 += rk[h + 3] * wq[(size_t)(h + 3) * NA];
            }
            qp[part][a] = (acc0 + acc1) + (acc2 + acc3);
        }
        __syncthreads();
        if (tid < NA) {
            qs[tid] = ((qp[0][tid] + qp[1][tid]) + (qp[2][tid] + qp[3][tid]))
                    + ((qp[4][tid] + qp[5][tid]) + (qp[6][tid] + qp[7][tid]));
        }
        __syncthreads();

        const int warp = tid >> 5, lane = tid & 31;
        const float4 q4 = reinterpret_cast<const float4*>(qs)[lane];
        const float4* __restrict__ wkbase =
            reinterpret_cast<const float4*>(Wk + ((size_t)k * NI) * NA);
        #pragma unroll
        for (int ii = 0; ii < 4; ++ii) {
            const int i = warp * 4 + ii;
            const float4 w4 = wkbase[(size_t)i * 32 + lane];
            float p = w4.x * q4.x + w4.y * q4.y + w4.z * q4.z + w4.w * q4.w;
            #pragma unroll
            for (int off = 16; off; off >>= 1) p += __shfl_xor_sync(0xffffffffu, p, off);
            if (lane == 0) g_u[k][i] = p;
        }
    } else {
        const int idx  = bid - KACT;
        const int k    = idx >> 1;
        const int half = idx & 1;
        const int h    = half * 128 + (tid & 127);
        const int part = tid >> 7;
        const float* __restrict__ rk = rim + k * NH + part * 32;
        const float* __restrict__ wh = Whh + (size_t)(part * 32) * NH + h;

        float acc0 = 0.f, acc1 = 0.f, acc2 = 0.f, acc3 = 0.f;
        #pragma unroll
        for (int hp = 0; hp < 32; hp += 4) {
            acc0 += rk[hp + 0] * wh[(size_t)(hp + 0) * NH];
            acc1 += rk[hp + 1] * wh[(size_t)(hp + 1) * NH];
            acc2 += rk[hp + 2] * wh[(size_t)(hp + 2) * NH];
            acc3 += rk[hp + 3] * wh[(size_t)(hp + 3) * NH];
        }
        __shared__ float hp_s[8][128];
        hp_s[part][tid & 127] = (acc0 + acc1) + (acc2 + acc3);
        __syncthreads();
        if (tid < 128) {
            float s = ((hp_s[0][tid] + hp_s[1][tid]) + (hp_s[2][tid] + hp_s[3][tid]))
                    + ((hp_s[4][tid] + hp_s[5][tid]) + (hp_s[6][tid] + hp_s[7][tid]));
            g_hpre[k][half * 128 + tid] = bias[half * 128 + tid] + s;
        }
    }
#if __CUDA_ARCH__ >= 900
    cudaTriggerProgrammaticLaunchCompletion();
#endif
}

// ---------------------------------------------------------------------------
// Main + elected epilogue. 1024 blocks x 256 thr, reg-capped for occupancy.
// PDL: prefetch x pre-sync; read g_u/g_hpre post-sync.
// ---------------------------------------------------------------------------
__global__ __launch_bounds__(256, 5) void main_kernel(
    const float* __restrict__ x,   const float* __restrict__ rim,
    const float* __restrict__ Wv,  const float* __restrict__ Wih,
    float* __restrict__ out)
{
    const int b     = blockIdx.x >> 5;
    const int chunk = blockIdx.x & 31;
    const int warp  = threadIdx.x >> 5;
    const int lane  = threadIdx.x & 31;
    const int tid   = threadIdx.x;

    const size_t row0 = (size_t)b * NS + chunk * ROWS_PER_BLOCK + warp * ROWS_PER_WARP;
    const float4* __restrict__ xr = reinterpret_cast<const float4*>(x + row0 * NI) + lane;

    // prefetch: x does not depend on prologue — legal pre-sync
    float4 pf[PREF];
    #pragma unroll
    for (int r = 0; r < PREF; ++r) pf[r] = xr[r * 32];

#if __CUDA_ARCH__ >= 900
    cudaGridDependencySynchronize();
#endif

    const float4 u0 = reinterpret_cast<const float4*>(g_u[0])[lane];
    const float4 u1 = reinterpret_cast<const float4*>(g_u[1])[lane];
    const float4 u2 = reinterpret_cast<const float4*>(g_u[2])[lane];

    float4 a0 = make_float4(0.f, 0.f, 0.f, 0.f);
    float4 a1 = a0, a2 = a0;

    #pragma unroll
    for (int r = 0; r < ROWS_PER_WARP; ++r) {
        const float4 v = (r < PREF) ? pf[r] : xr[r * 32];
        float d0 = v.x * u0.x + v.y * u0.y + v.z * u0.z + v.w * u0.w;
        float d1 = v.x * u1.x + v.y * u1.y + v.z * u1.z + v.w * u1.w;
        float d2 = v.x * u2.x + v.y * u2.y + v.z * u2.z + v.w * u2.w;
        #pragma unroll
        for (int off = 16; off; off >>= 1) {
            d0 += __shfl_xor_sync(0xffffffffu, d0, off);
            d1 += __shfl_xor_sync(0xffffffffu, d1, off);
            d2 += __shfl_xor_sync(0xffffffffu, d2, off);
        }
        a0.x += d0 * v.x; a0.y += d0 * v.y; a0.z += d0 * v.z; a0.w += d0 * v.w;
        a1.x += d1 * v.x; a1.y += d1 * v.y; a1.z += d1 * v.z; a1.w += d1 * v.w;
        a2.x += d2 * v.x; a2.y += d2 * v.y; a2.z += d2 * v.z; a2.w += d2 * v.w;
    }

    __shared__ __align__(16) float pool[8 * KACT * NI];   // 12 KB, reused
    float (*ysw)[KACT * NI] = (float(*)[KACT * NI])pool;
    reinterpret_cast<float4*>(&ysw[warp][0 * NI])[lane] = a0;
    reinterpret_cast<float4*>(&ysw[warp][1 * NI])[lane] = a1;
    reinterpret_cast<float4*>(&ysw[warp][2 * NI])[lane] = a2;
    __syncthreads();

    if (tid < 96) {
        const float4* __restrict__ base = reinterpret_cast<const float4*>(pool);
        float4 s = base[tid];
        #pragma unroll
        for (int w = 1; w < 8; ++w) {
            const float4 t = base[w * 96 + tid];
            s.x += t.x; s.y += t.y; s.z += t.z; s.w += t.w;
        }
        reinterpret_cast<float4*>(&g_ypart[b][chunk][0])[tid] = s;
    }
    __threadfence();
    __syncthreads();

    // ---- election: 32nd arrival for this b runs the epilogue; resets counter
    __shared__ int elect;
    if (tid == 0) {
        const int v = atomicAdd(&g_bcnt[b], 1);
        elect = (v == CHUNKS - 1);
        if (v == CHUNKS - 1) g_bcnt[b] = 0;   // safe: no more arrivals this replay
    }
    __syncthreads();
    if (!elect) return;

    // ================= EPILOGUE for batch b (all 3 k) =================
    float* ys   = pool;          // 384
    float* att  = pool + 384;    // 384
    float* attp = pool + 768;    // 768

    // ys[k*128+i] = sum over 32 chunks (deterministic order)
    for (int j = tid; j < KACT * NI; j += 256) {
        const float* __restrict__ yp = &g_ypart[b][0][j];
        float s0 = __ldcg(yp + 0 * (KACT * NI));
        float s1 = __ldcg(yp + 8 * (KACT * NI));
        float s2 = __ldcg(yp + 16 * (KACT * NI));
        float s3 = __ldcg(yp + 24 * (KACT * NI));
        #pragma unroll
        for (int c = 1; c < 8; ++c) {
            s0 += __ldcg(yp + (c + 0)  * (KACT * NI));
            s1 += __ldcg(yp + (c + 8)  * (KACT * NI));
            s2 += __ldcg(yp + (c + 16) * (KACT * NI));
            s3 += __ldcg(yp + (c + 24) * (KACT * NI));
        }
        ys[j] = (s0 + s1) + (s2 + s3);
    }
    __syncthreads();

    // att[k][a] = sum_i Wv[k][i][a] * ys[k][i], 2-way i split (768 tasks)
    for (int t = tid; t < 2 * KACT * NA; t += 256) {
        const int half = t / (KACT * NA);
        const int jj   = t - half * (KACT * NA);
        const int k = jj >> 7, a = jj & 127;
        const float* __restrict__ wv =
            Wv + (size_t)k * NI * NA + (size_t)(half * 64) * NA + a;
        const float* __restrict__ yk = ys + k * NI + half * 64;
        float c0 = 0.f, c1 = 0.f, c2 = 0.f, c3 = 0.f;
        #pragma unroll
        for (int i = 0; i < 64; i += 4) {
            c0 += wv[(size_t)(i + 0) * NA] * yk[i + 0];
            c1 += wv[(size_t)(i + 1) * NA] * yk[i + 1];
            c2 += wv[(size_t)(i + 2) * NA] * yk[i + 2];
            c3 += wv[(size_t)(i + 3) * NA] * yk[i + 3];
        }
        attp[t] = (c0 + c1) + (c2 + c3);
    }
    __syncthreads();
    for (int j = tid; j < KACT * NA; j += 256)
        att[j] = attp[j] + attp[KACT * NA + j];
    __syncthreads();

    float* ob = out + (size_t)b * NK * NH;

    // cand: 768 outputs, 128-long reduce, 4 accumulators
    for (int t = tid; t < KACT * NH; t += 256) {
        const int k = t >> 8, h = t & 255;
        const float* __restrict__ ak = att + k * NA;
        const float* __restrict__ wih = Wih + h;
        float c0 = __ldcg(&g_hpre[k][h]), c1 = 0.f, c2 = 0.f, c3 = 0.f;
        #pragma unroll
        for (int a = 0; a < NA; a += 4) {
            c0 += ak[a + 0] * wih[(size_t)(a + 0) * NH];
            c1 += ak[a + 1] * wih[(size_t)(a + 1) * NH];
            c2 += ak[a + 2] * wih[(size_t)(a + 2) * NH];
            c3 += ak[a + 3] * wih[(size_t)(a + 3) * NH];
        }
        ob[t] = tanhf((c0 + c1) + (c2 + c3));
    }
    // passthrough k = 3..7 (1280 floats, float4)
    {
        const float4* __restrict__ r4 = reinterpret_cast<const float4*>(rim + KACT * NH);
        float4* __restrict__ o4 = reinterpret_cast<float4*>(ob + KACT * NH);
        for (int j = tid; j < (NK - KACT) * NH / 4; j += 256)
            o4[j] = r4[j];
    }
}

// ---------------------------------------------------------------------------
extern "C" void kernel_launch(void* const* d_in, const int* in_sizes, int n_in,
                              void* d_out, int out_size)
{
    const float* x    = (const float*)d_in[0];
    const float* rim  = (const float*)d_in[1];
    const float* Wq   = (const float*)d_in[2];
    const float* Wk   = (const float*)d_in[3];
    const float* Wv   = (const float*)d_in[4];
    const float* Wih  = (const float*)d_in[5];
    const float* Whh  = (const float*)d_in[6];
    const float* bias = (const float*)d_in[7];
    float* out = (float*)d_out;

    // node 1: prologue
    prologue_kernel<<<KACT + 2 * KACT, 1024>>>(rim, Wq, Wk, Whh, bias);

    // node 2: main+epilogue with PDL
    {
        cudaLaunchConfig_t cfg = {};
        cfg.gridDim  = dim3(NB * CHUNKS);
        cfg.blockDim = dim3(256);
        cudaLaunchAttribute attr[1];
        attr[0].id = cudaLaunchAttributeProgrammaticStreamSerialization;
        attr[0].val.programmaticStreamSerializationAllowed = 1;
        cfg.attrs = attr;
        cfg.numAttrs = 1;
        cudaLaunchKernelEx(&cfg, main_kernel, x, rim, Wv, Wih, out);
    }
}

// round 11
// speedup vs baseline: 1.0366x; 1.0366x over previous
#include <cuda_runtime.h>
#include <cuda_bf16.h>

// Shapes: B=32, S=2048, I=128, A=128, H=256, K=8, ACTIVE=3 (structurally k=0,1,2)
#define NB 32
#define NS 2048
#define NI 128
#define NA 128
#define NH 256
#define NK 8
#define KACT 3
#define CHUNKS 32
#define ROWS_PER_BLOCK (NS / CHUNKS)       // 64
#define ROWS_PER_WARP (ROWS_PER_BLOCK / 8) // 8
#define PREF 4

// Device scratch (allocation-free rule: __device__ globals; zero-initialized)
__device__ float g_u[KACT][NI];
__device__ float g_hpre[KACT][NH];
__device__ __align__(16) float g_ypart[NB][CHUNKS][KACT * NI];
__device__ int   g_bcnt[NB];

// ---------------------------------------------------------------------------
// Prologue (9 blocks x 1024 threads):
//   blocks 0..2 : k-block. q[k][a] = sum_h rim*Wq, then u[k][i] = Wk[k][i][:].q
//   blocks 3..8 : (k, h-half) hpre
// ---------------------------------------------------------------------------
__global__ __launch_bounds__(1024) void prologue_kernel(
    const float* __restrict__ rim, const float* __restrict__ Wq,
    const float* __restrict__ Wk, const float* __restrict__ Whh,
    const float* __restrict__ bias)
{
    const int tid = threadIdx.x;
    const int bid = blockIdx.x;

    if (bid < KACT) {
        const int k = bid;
        __shared__ float qp[8][NA];
        __shared__ __align__(16) float qs[NA];

        {
            const int a    = tid & 127;
            const int part = tid >> 7;
            const int h0   = part * 32;
            const float* __restrict__ wq = Wq + ((size_t)(k * NH + h0)) * NA + a;
            const float* __restrict__ rk = rim + k * NH + h0;
            float acc0 = 0.f, acc1 = 0.f, acc2 = 0.f, acc3 = 0.f;
            #pragma unroll
            for (int h = 0; h < 32; h += 4) {
                acc0 += rk[h + 0] * wq[(size_t)(h + 0) * NA];
                acc1 += rk[h + 1] * wq[(size_t)(h + 1) * NA];
                acc2 += rk[h + 2] * wq[(size_t)(h + 2) * NA];
                acc3 += rk[h + 3] * wq[(size_t)(h + 3) * NA];
            }
            qp[part][a] = (acc0 + acc1) + (acc2 + acc3);
        }
        __syncthreads();
        if (tid < NA) {
            qs[tid] = ((qp[0][tid] + qp[1][tid]) + (qp[2][tid] + qp[3][tid]))
                    + ((qp[4][tid] + qp[5][tid]) + (qp[6][tid] + qp[7][tid]));
        }
        __syncthreads();

        const int warp = tid >> 5, lane = tid & 31;
        const float4 q4 = reinterpret_cast<const float4*>(qs)[lane];
        const float4* __restrict__ wkbase =
            reinterpret_cast<const float4*>(Wk + ((size_t)k * NI) * NA);
        #pragma unroll
        for (int ii = 0; ii < 4; ++ii) {
            const int i = warp * 4 + ii;
            const float4 w4 = wkbase[(size_t)i * 32 + lane];
            float p = w4.x * q4.x + w4.y * q4.y + w4.z * q4.z + w4.w * q4.w;
            #pragma unroll
            for (int off = 16; off; off >>= 1) p += __shfl_xor_sync(0xffffffffu, p, off);
            if (lane == 0) g_u[k][i] = p;
        }
    } else {
        const int idx  = bid - KACT;
        const int k    = idx >> 1;
        const int half = idx & 1;
        const int h    = half * 128 + (tid & 127);
        const int part = tid >> 7;
        const float* __restrict__ rk = rim + k * NH + part * 32;
        const float* __restrict__ wh = Whh + (size_t)(part * 32) * NH + h;

        float acc0 = 0.f, acc1 = 0.f, acc2 = 0.f, acc3 = 0.f;
        #pragma unroll
        for (int hp = 0; hp < 32; hp += 4) {
            acc0 += rk[hp + 0] * wh[(size_t)(hp + 0) * NH];
            acc1 += rk[hp + 1] * wh[(size_t)(hp + 1) * NH];
            acc2 += rk[hp + 2] * wh[(size_t)(hp + 2) * NH];
            acc3 += rk[hp + 3] * wh[(size_t)(hp + 3) * NH];
        }
        __shared__ float hp_s[8][128];
        hp_s[part][tid & 127] = (acc0 + acc1) + (acc2 + acc3);
        __syncthreads();
        if (tid < 128) {
            float s = ((hp_s[0][tid] + hp_s[1][tid]) + (hp_s[2][tid] + hp_s[3][tid]))
                    + ((hp_s[4][tid] + hp_s[5][tid]) + (hp_s[6][tid] + hp_s[7][tid]));
            g_hpre[k][half * 128 + tid] = bias[half * 128 + tid] + s;
        }
    }
#if __CUDA_ARCH__ >= 900
    cudaTriggerProgrammaticLaunchCompletion();
#endif
}

// ---------------------------------------------------------------------------
// Main + elected epilogue. 1024 blocks x 256 thr, reg-capped for occupancy.
// PDL: prefetch x pre-sync; read g_u/g_hpre post-sync.
// ---------------------------------------------------------------------------
__global__ __launch_bounds__(256, 5) void main_kernel(
    const float* __restrict__ x,   const float* __restrict__ rim,
    const float* __restrict__ Wv,  const float* __restrict__ Wih,
    float* __restrict__ out)
{
    const int b     = blockIdx.x >> 5;
    const int chunk = blockIdx.x & 31;
    const int warp  = threadIdx.x >> 5;
    const int lane  = threadIdx.x & 31;
    const int tid   = threadIdx.x;

    const size_t row0 = (size_t)b * NS + chunk * ROWS_PER_BLOCK + warp * ROWS_PER_WARP;
    const float4* __restrict__ xr = reinterpret_cast<const float4*>(x + row0 * NI) + lane;

    // prefetch: x does not depend on prologue — legal pre-sync
    float4 pf[PREF];
    #pragma unroll
    for (int r = 0; r < PREF; ++r) pf[r] = xr[r * 32];

#if __CUDA_ARCH__ >= 900
    cudaGridDependencySynchronize();
#endif

    const float4 u0 = reinterpret_cast<const float4*>(g_u[0])[lane];
    const float4 u1 = reinterpret_cast<const float4*>(g_u[1])[lane];
    const float4 u2 = reinterpret_cast<const float4*>(g_u[2])[lane];

    float4 a0 = make_float4(0.f, 0.f, 0.f, 0.f);
    float4 a1 = a0, a2 = a0;

    #pragma unroll
    for (int r = 0; r < ROWS_PER_WARP; ++r) {
        const float4 v = (r < PREF) ? pf[r] : xr[r * 32];
        float d0 = v.x * u0.x + v.y * u0.y + v.z * u0.z + v.w * u0.w;
        float d1 = v.x * u1.x + v.y * u1.y + v.z * u1.z + v.w * u1.w;
        float d2 = v.x * u2.x + v.y * u2.y + v.z * u2.z + v.w * u2.w;
        #pragma unroll
        for (int off = 16; off; off >>= 1) {
            d0 += __shfl_xor_sync(0xffffffffu, d0, off);
            d1 += __shfl_xor_sync(0xffffffffu, d1, off);
            d2 += __shfl_xor_sync(0xffffffffu, d2, off);
        }
        a0.x += d0 * v.x; a0.y += d0 * v.y; a0.z += d0 * v.z; a0.w += d0 * v.w;
        a1.x += d1 * v.x; a1.y += d1 * v.y; a1.z += d1 * v.z; a1.w += d1 * v.w;
        a2.x += d2 * v.x; a2.y += d2 * v.y; a2.z += d2 * v.z; a2.w += d2 * v.w;
    }

    __shared__ __align__(16) float pool[8 * KACT * NI];   // 12 KB, reused
    float (*ysw)[KACT * NI] = (float(*)[KACT * NI])pool;
    reinterpret_cast<float4*>(&ysw[warp][0 * NI])[lane] = a0;
    reinterpret_cast<float4*>(&ysw[warp][1 * NI])[lane] = a1;
    reinterpret_cast<float4*>(&ysw[warp][2 * NI])[lane] = a2;
    __syncthreads();

    if (tid < 96) {
        const float4* __restrict__ base = reinterpret_cast<const float4*>(pool);
        float4 s = base[tid];
        #pragma unroll
        for (int w = 1; w < 8; ++w) {
            const float4 t = base[w * 96 + tid];
            s.x += t.x; s.y += t.y; s.z += t.z; s.w += t.w;
        }
        reinterpret_cast<float4*>(&g_ypart[b][chunk][0])[tid] = s;
    }
    __threadfence();
    __syncthreads();

    // ---- election: 32nd arrival for this b runs the epilogue; resets counter
    __shared__ int elect;
    if (tid == 0) {
        const int v = atomicAdd(&g_bcnt[b], 1);
        elect = (v == CHUNKS - 1);
        if (v == CHUNKS - 1) g_bcnt[b] = 0;   // safe: no more arrivals this replay
    }
    __syncthreads();
    if (!elect) return;

    // ================= EPILOGUE for batch b (all 3 k) =================
    float* ys   = pool;          // 384
    float* att  = pool + 384;    // 384
    float* attp = pool + 768;    // 768

    // ys[k*128+i] = sum over 32 chunks (deterministic order)
    for (int j = tid; j < KACT * NI; j += 256) {
        const float* __restrict__ yp = &g_ypart[b][0][j];
        float s0 = __ldcg(yp + 0 * (KACT * NI));
        float s1 = __ldcg(yp + 8 * (KACT * NI));
        float s2 = __ldcg(yp + 16 * (KACT * NI));
        float s3 = __ldcg(yp + 24 * (KACT * NI));
        #pragma unroll
        for (int c = 1; c < 8; ++c) {
            s0 += __ldcg(yp + (c + 0)  * (KACT * NI));
            s1 += __ldcg(yp + (c + 8)  * (KACT * NI));
            s2 += __ldcg(yp + (c + 16) * (KACT * NI));
            s3 += __ldcg(yp + (c + 24) * (KACT * NI));
        }
        ys[j] = (s0 + s1) + (s2 + s3);
    }
    __syncthreads();

    // att[k][a] = sum_i Wv[k][i][a] * ys[k][i], 2-way i split (768 tasks)
    for (int t = tid; t < 2 * KACT * NA; t += 256) {
        const int half = t / (KACT * NA);
        const int jj   = t - half * (KACT * NA);
        const int k = jj >> 7, a = jj & 127;
        const float* __restrict__ wv =
            Wv + (size_t)k * NI * NA + (size_t)(half * 64) * NA + a;
        const float* __restrict__ yk = ys + k * NI + half * 64;
        float c0 = 0.f, c1 = 0.f, c2 = 0.f, c3 = 0.f;
        #pragma unroll
        for (int i = 0; i < 64; i += 4) {
            c0 += wv[(size_t)(i + 0) * NA] * yk[i + 0];
            c1 += wv[(size_t)(i + 1) * NA] * yk[i + 1];
            c2 += wv[(size_t)(i + 2) * NA] * yk[i + 2];
            c3 += wv[(size_t)(i + 3) * NA] * yk[i + 3];
        }
        attp[t] = (c0 + c1) + (c2 + c3);
    }
    __syncthreads();
    for (int j = tid; j < KACT * NA; j += 256)
        att[j] = attp[j] + attp[KACT * NA + j];
    __syncthreads();

    float* ob = out + (size_t)b * NK * NH;

    // cand: 768 outputs, 128-long reduce, 4 accumulators
    for (int t = tid; t < KACT * NH; t += 256) {
        const int k = t >> 8, h = t & 255;
        const float* __restrict__ ak = att + k * NA;
        const float* __restrict__ wih = Wih + h;
        float c0 = __ldcg(&g_hpre[k][h]), c1 = 0.f, c2 = 0.f, c3 = 0.f;
        #pragma unroll
        for (int a = 0; a < NA; a += 4) {
            c0 += ak[a + 0] * wih[(size_t)(a + 0) * NH];
            c1 += ak[a + 1] * wih[(size_t)(a + 1) * NH];
            c2 += ak[a + 2] * wih[(size_t)(a + 2) * NH];
            c3 += ak[a + 3] * wih[(size_t)(a + 3) * NH];
        }
        ob[t] = tanhf((c0 + c1) + (c2 + c3));
    }
    // passthrough k = 3..7 (1280 floats, float4)
    {
        const float4* __restrict__ r4 = reinterpret_cast<const float4*>(rim + KACT * NH);
        float4* __restrict__ o4 = reinterpret_cast<float4*>(ob + KACT * NH);
        for (int j = tid; j < (NK - KACT) * NH / 4; j += 256)
            o4[j] = r4[j];
    }
}

// ---------------------------------------------------------------------------
extern "C" void kernel_launch(void* const* d_in, const int* in_sizes, int n_in,
                              void* d_out, int out_size)
{
    const float* x    = (const float*)d_in[0];
    const float* rim  = (const float*)d_in[1];
    const float* Wq   = (const float*)d_in[2];
    const float* Wk   = (const float*)d_in[3];
    const float* Wv   = (const float*)d_in[4];
    const float* Wih  = (const float*)d_in[5];
    const float* Whh  = (const float*)d_in[6];
    const float* bias = (const float*)d_in[7];
    float* out = (float*)d_out;

    // node 1: prologue
    prologue_kernel<<<KACT + 2 * KACT, 1024>>>(rim, Wq, Wk, Whh, bias);

    // node 2: main+epilogue with PDL
    {
        cudaLaunchConfig_t cfg = {};
        cfg.gridDim  = dim3(NB * CHUNKS);
        cfg.blockDim = dim3(256);
        cudaLaunchAttribute attr[1];
        attr[0].id = cudaLaunchAttributeProgrammaticStreamSerialization;
        attr[0].val.programmaticStreamSerializationAllowed = 1;
        cfg.attrs = attr;
        cfg.numAttrs = 1;
        cudaLaunchKernelEx(&cfg, main_kernel, x, rim, Wv, Wih, out);
    }
}

// round 12
// speedup vs baseline: 1.0412x; 1.0044x over previous
#include <cuda_runtime.h>
#include <cuda_bf16.h>

// Shapes: B=32, S=2048, I=128, A=128, H=256, K=8, ACTIVE=3 (structurally k=0,1,2)
#define NB 32
#define NS 2048
#define NI 128
#define NA 128
#define NH 256
#define NK 8
#define KACT 3
#define CHUNKS 32
#define ROWS_PER_BLOCK (NS / CHUNKS)       // 64
#define ROWS_PER_WARP (ROWS_PER_BLOCK / 8) // 8
#define PREF 4

// Device scratch (allocation-free rule: __device__ globals; zero-initialized)
__device__ float g_u[KACT][NI];
__device__ float g_hpre[KACT][NH];
__device__ __align__(16) float g_ypart[NB][CHUNKS][KACT * NI];
__device__ int   g_bcnt[NB];

// ---------------------------------------------------------------------------
// Prologue (9 blocks x 1024 threads):
//   blocks 0..2 : k-block. q[k][a] = sum_h rim*Wq, then u[k][i] = Wk[k][i][:].q
//   blocks 3..8 : (k, h-half) hpre
// ---------------------------------------------------------------------------
__global__ __launch_bounds__(1024) void prologue_kernel(
    const float* __restrict__ rim, const float* __restrict__ Wq,
    const float* __restrict__ Wk, const float* __restrict__ Whh,
    const float* __restrict__ bias)
{
    const int tid = threadIdx.x;
    const int bid = blockIdx.x;

    if (bid < KACT) {
        const int k = bid;
        __shared__ float qp[8][NA];
        __shared__ __align__(16) float qs[NA];

        {
            const int a    = tid & 127;
            const int part = tid >> 7;
            const int h0   = part * 32;
            const float* __restrict__ wq = Wq + ((size_t)(k * NH + h0)) * NA + a;
            const float* __restrict__ rk = rim + k * NH + h0;
            float acc0 = 0.f, acc1 = 0.f, acc2 = 0.f, acc3 = 0.f;
            #pragma unroll
            for (int h = 0; h < 32; h += 4) {
                acc0 += rk[h + 0] * wq[(size_t)(h + 0) * NA];
                acc1 += rk[h + 1] * wq[(size_t)(h + 1) * NA];
                acc2 += rk[h + 2] * wq[(size_t)(h + 2) * NA];
                acc3 += rk[h + 3] * wq[(size_t)(h + 3) * NA];
            }
            qp[part][a] = (acc0 + acc1) + (acc2 + acc3);
        }
        __syncthreads();
        if (tid < NA) {
            qs[tid] = ((qp[0][tid] + qp[1][tid]) + (qp[2][tid] + qp[3][tid]))
                    + ((qp[4][tid] + qp[5][tid]) + (qp[6][tid] + qp[7][tid]));
        }
        __syncthreads();

        const int warp = tid >> 5, lane = tid & 31;
        const float4 q4 = reinterpret_cast<const float4*>(qs)[lane];
        const float4* __restrict__ wkbase =
            reinterpret_cast<const float4*>(Wk + ((size_t)k * NI) * NA);
        #pragma unroll
        for (int ii = 0; ii < 4; ++ii) {
            const int i = warp * 4 + ii;
            const float4 w4 = wkbase[(size_t)i * 32 + lane];
            float p = w4.x * q4.x + w4.y * q4.y + w4.z * q4.z + w4.w * q4.w;
            #pragma unroll
            for (int off = 16; off; off >>= 1) p += __shfl_xor_sync(0xffffffffu, p, off);
            if (lane == 0) g_u[k][i] = p;
        }
    } else {
        const int idx  = bid - KACT;
        const int k    = idx >> 1;
        const int half = idx & 1;
        const int h    = half * 128 + (tid & 127);
        const int part = tid >> 7;
        const float* __restrict__ rk = rim + k * NH + part * 32;
        const float* __restrict__ wh = Whh + (size_t)(part * 32) * NH + h;

        float acc0 = 0.f, acc1 = 0.f, acc2 = 0.f, acc3 = 0.f;
        #pragma unroll
        for (int hp = 0; hp < 32; hp += 4) {
            acc0 += rk[hp + 0] * wh[(size_t)(hp + 0) * NH];
            acc1 += rk[hp + 1] * wh[(size_t)(hp + 1) * NH];
            acc2 += rk[hp + 2] * wh[(size_t)(hp + 2) * NH];
            acc3 += rk[hp + 3] * wh[(size_t)(hp + 3) * NH];
        }
        __shared__ float hp_s[8][128];
        hp_s[part][tid & 127] = (acc0 + acc1) + (acc2 + acc3);
        __syncthreads();
        if (tid < 128) {
            float s = ((hp_s[0][tid] + hp_s[1][tid]) + (hp_s[2][tid] + hp_s[3][tid]))
                    + ((hp_s[4][tid] + hp_s[5][tid]) + (hp_s[6][tid] + hp_s[7][tid]));
            g_hpre[k][half * 128 + tid] = bias[half * 128 + tid] + s;
        }
    }
#if __CUDA_ARCH__ >= 900
    cudaTriggerProgrammaticLaunchCompletion();
#endif
}

// ---------------------------------------------------------------------------
// Main + elected epilogue. 1024 blocks x 256 thr, reg-capped for occupancy.
// PDL: prefetch x pre-sync; read g_u/g_hpre post-sync.
// ---------------------------------------------------------------------------
__global__ __launch_bounds__(256, 5) void main_kernel(
    const float* __restrict__ x,   const float* __restrict__ rim,
    const float* __restrict__ Wv,  const float* __restrict__ Wih,
    float* __restrict__ out)
{
    const int b     = blockIdx.x >> 5;
    const int chunk = blockIdx.x & 31;
    const int warp  = threadIdx.x >> 5;
    const int lane  = threadIdx.x & 31;
    const int tid   = threadIdx.x;

    const size_t row0 = (size_t)b * NS + chunk * ROWS_PER_BLOCK + warp * ROWS_PER_WARP;
    const float4* __restrict__ xr = reinterpret_cast<const float4*>(x + row0 * NI) + lane;

    // prefetch: x does not depend on prologue — legal pre-sync
    float4 pf[PREF];
    #pragma unroll
    for (int r = 0; r < PREF; ++r) pf[r] = xr[r * 32];

#if __CUDA_ARCH__ >= 900
    cudaGridDependencySynchronize();
#endif

    const float4 u0 = reinterpret_cast<const float4*>(g_u[0])[lane];
    const float4 u1 = reinterpret_cast<const float4*>(g_u[1])[lane];
    const float4 u2 = reinterpret_cast<const float4*>(g_u[2])[lane];

    float4 a0 = make_float4(0.f, 0.f, 0.f, 0.f);
    float4 a1 = a0, a2 = a0;

    #pragma unroll
    for (int r = 0; r < ROWS_PER_WARP; ++r) {
        const float4 v = (r < PREF) ? pf[r] : xr[r * 32];
        float d0 = v.x * u0.x + v.y * u0.y + v.z * u0.z + v.w * u0.w;
        float d1 = v.x * u1.x + v.y * u1.y + v.z * u1.z + v.w * u1.w;
        float d2 = v.x * u2.x + v.y * u2.y + v.z * u2.z + v.w * u2.w;
        #pragma unroll
        for (int off = 16; off; off >>= 1) {
            d0 += __shfl_xor_sync(0xffffffffu, d0, off);
            d1 += __shfl_xor_sync(0xffffffffu, d1, off);
            d2 += __shfl_xor_sync(0xffffffffu, d2, off);
        }
        a0.x += d0 * v.x; a0.y += d0 * v.y; a0.z += d0 * v.z; a0.w += d0 * v.w;
        a1.x += d1 * v.x; a1.y += d1 * v.y; a1.z += d1 * v.z; a1.w += d1 * v.w;
        a2.x += d2 * v.x; a2.y += d2 * v.y; a2.z += d2 * v.z; a2.w += d2 * v.w;
    }

    __shared__ __align__(16) float pool[8 * KACT * NI];   // 12 KB, reused
    float (*ysw)[KACT * NI] = (float(*)[KACT * NI])pool;
    reinterpret_cast<float4*>(&ysw[warp][0 * NI])[lane] = a0;
    reinterpret_cast<float4*>(&ysw[warp][1 * NI])[lane] = a1;
    reinterpret_cast<float4*>(&ysw[warp][2 * NI])[lane] = a2;
    __syncthreads();

    if (tid < 96) {
        const float4* __restrict__ base = reinterpret_cast<const float4*>(pool);
        float4 s = base[tid];
        #pragma unroll
        for (int w = 1; w < 8; ++w) {
            const float4 t = base[w * 96 + tid];
            s.x += t.x; s.y += t.y; s.z += t.z; s.w += t.w;
        }
        reinterpret_cast<float4*>(&g_ypart[b][chunk][0])[tid] = s;
    }
    __threadfence();
    __syncthreads();

    // ---- election: 32nd arrival for this b runs the epilogue; resets counter
    __shared__ int elect;
    if (tid == 0) {
        const int v = atomicAdd(&g_bcnt[b], 1);
        elect = (v == CHUNKS - 1);
        if (v == CHUNKS - 1) g_bcnt[b] = 0;   // safe: no more arrivals this replay
    }
    __syncthreads();
    if (!elect) return;

    // ================= EPILOGUE for batch b (all 3 k) =================
    float* ys   = pool;          // 384
    float* att  = pool + 384;    // 384
    float* attp = pool + 768;    // 768

    // ys[k*128+i] = sum over 32 chunks (deterministic order)
    for (int j = tid; j < KACT * NI; j += 256) {
        const float* __restrict__ yp = &g_ypart[b][0][j];
        float s0 = __ldcg(yp + 0 * (KACT * NI));
        float s1 = __ldcg(yp + 8 * (KACT * NI));
        float s2 = __ldcg(yp + 16 * (KACT * NI));
        float s3 = __ldcg(yp + 24 * (KACT * NI));
        #pragma unroll
        for (int c = 1; c < 8; ++c) {
            s0 += __ldcg(yp + (c + 0)  * (KACT * NI));
            s1 += __ldcg(yp + (c + 8)  * (KACT * NI));
            s2 += __ldcg(yp + (c + 16) * (KACT * NI));
            s3 += __ldcg(yp + (c + 24) * (KACT * NI));
        }
        ys[j] = (s0 + s1) + (s2 + s3);
    }
    __syncthreads();

    // att[k][a] = sum_i Wv[k][i][a] * ys[k][i], 2-way i split (768 tasks)
    for (int t = tid; t < 2 * KACT * NA; t += 256) {
        const int half = t / (KACT * NA);
        const int jj   = t - half * (KACT * NA);
        const int k = jj >> 7, a = jj & 127;
        const float* __restrict__ wv =
            Wv + (size_t)k * NI * NA + (size_t)(half * 64) * NA + a;
        const float* __restrict__ yk = ys + k * NI + half * 64;
        float c0 = 0.f, c1 = 0.f, c2 = 0.f, c3 = 0.f;
        #pragma unroll
        for (int i = 0; i < 64; i += 4) {
            c0 += wv[(size_t)(i + 0) * NA] * yk[i + 0];
            c1 += wv[(size_t)(i + 1) * NA] * yk[i + 1];
            c2 += wv[(size_t)(i + 2) * NA] * yk[i + 2];
            c3 += wv[(size_t)(i + 3) * NA] * yk[i + 3];
        }
        attp[t] = (c0 + c1) + (c2 + c3);
    }
    __syncthreads();
    for (int j = tid; j < KACT * NA; j += 256)
        att[j] = attp[j] + attp[KACT * NA + j];
    __syncthreads();

    float* ob = out + (size_t)b * NK * NH;

    // cand: 768 outputs, 128-long reduce, 4 accumulators
    for (int t = tid; t < KACT * NH; t += 256) {
        const int k = t >> 8, h = t & 255;
        const float* __restrict__ ak = att + k * NA;
        const float* __restrict__ wih = Wih + h;
        float c0 = __ldcg(&g_hpre[k][h]), c1 = 0.f, c2 = 0.f, c3 = 0.f;
        #pragma unroll
        for (int a = 0; a < NA; a += 4) {
            c0 += ak[a + 0] * wih[(size_t)(a + 0) * NH];
            c1 += ak[a + 1] * wih[(size_t)(a + 1) * NH];
            c2 += ak[a + 2] * wih[(size_t)(a + 2) * NH];
            c3 += ak[a + 3] * wih[(size_t)(a + 3) * NH];
        }
        ob[t] = tanhf((c0 + c1) + (c2 + c3));
    }
    // passthrough k = 3..7 (1280 floats, float4)
    {
        const float4* __restrict__ r4 = reinterpret_cast<const float4*>(rim + KACT * NH);
        float4* __restrict__ o4 = reinterpret_cast<float4*>(ob + KACT * NH);
        for (int j = tid; j < (NK - KACT) * NH / 4; j += 256)
            o4[j] = r4[j];
    }
}

// ---------------------------------------------------------------------------
extern "C" void kernel_launch(void* const* d_in, const int* in_sizes, int n_in,
                              void* d_out, int out_size)
{
    const float* x    = (const float*)d_in[0];
    const float* rim  = (const float*)d_in[1];
    const float* Wq   = (const float*)d_in[2];
    const float* Wk   = (const float*)d_in[3];
    const float* Wv   = (const float*)d_in[4];
    const float* Wih  = (const float*)d_in[5];
    const float* Whh  = (const float*)d_in[6];
    const float* bias = (const float*)d_in[7];
    float* out = (float*)d_out;

    // node 1: prologue
    prologue_kernel<<<KACT + 2 * KACT, 1024>>>(rim, Wq, Wk, Whh, bias);

    // node 2: main+epilogue with PDL
    {
        cudaLaunchConfig_t cfg = {};
        cfg.gridDim  = dim3(NB * CHUNKS);
        cfg.blockDim = dim3(256);
        cudaLaunchAttribute attr[1];
        attr[0].id = cudaLaunchAttributeProgrammaticStreamSerialization;
        attr[0].val.programmaticStreamSerializationAllowed = 1;
        cfg.attrs = attr;
        cfg.numAttrs = 1;
        cudaLaunchKernelEx(&cfg, main_kernel, x, rim, Wv, Wih, out);
    }
}